// round 7
// baseline (speedup 1.0000x reference)
#include <cuda_runtime.h>
#include <cstdint>

// ---------------------------------------------------------------------------
// C=12, L=32, D=32, NOUT=2. Counts are int32 on device (JAX x64-off).
// scan   : exclusive offsets of counts -> g_offs
// phase1 : dense per-read q[r][2] = W2_s . relu(W x_r + b) summed over L.
//          Direct LDG.128 into MMA B-fragments (no smem staging at all).
// phase2 : warp-per-allele ragged reduce of q + normalize + bias.
// ---------------------------------------------------------------------------

#define MAXR 131072
#define MAXA 16384
__device__ float2 g_q0[MAXR];
__device__ float2 g_q1[MAXR];
__device__ int g_offs0[MAXA];
__device__ int g_offs1[MAXA];

__device__ __forceinline__ uint32_t f2tf32(float f) {
    uint32_t u;
    asm("cvt.rna.tf32.f32 %0, %1;" : "=r"(u) : "f"(f));
    return u;
}

__device__ __forceinline__ void mma_tf32(float c[4], const uint32_t a[4],
                                         uint32_t b0, uint32_t b1) {
    asm volatile(
        "mma.sync.aligned.m16n8k8.row.col.f32.tf32.tf32.f32 "
        "{%0,%1,%2,%3},{%4,%5,%6,%7},{%8,%9},{%0,%1,%2,%3};"
        : "+f"(c[0]), "+f"(c[1]), "+f"(c[2]), "+f"(c[3])
        : "r"(a[0]), "r"(a[1]), "r"(a[2]), "r"(a[3]), "r"(b0), "r"(b1));
}

// ---------------------------------------------------------------------------
// Offsets scan: one block of 256 threads, serial chunk + Hillis-Steele.
// ---------------------------------------------------------------------------
__global__ __launch_bounds__(256) void rc_scan(const int* __restrict__ c0,
                                               const int* __restrict__ c1,
                                               int A) {
    __shared__ int s0[256], s1[256];
    const int t = threadIdx.x;
    const int per = (A + 255) >> 8;
    const int base = t * per;
    int l0 = 0, l1 = 0;
    for (int i = 0; i < per; i++) {
        int idx = base + i;
        if (idx < A) { l0 += c0[idx]; l1 += c1[idx]; }
    }
    s0[t] = l0; s1[t] = l1;
    __syncthreads();
    #pragma unroll
    for (int o = 1; o < 256; o <<= 1) {
        int v0 = (t >= o) ? s0[t - o] : 0;
        int v1 = (t >= o) ? s1[t - o] : 0;
        __syncthreads();
        s0[t] += v0; s1[t] += v1;
        __syncthreads();
    }
    int ex0 = t ? s0[t - 1] : 0;
    int ex1 = t ? s1[t - 1] : 0;
    for (int i = 0; i < per; i++) {
        int idx = base + i;
        if (idx < A) {
            g_offs0[idx] = ex0; g_offs1[idx] = ex1;
            ex0 += c0[idx]; ex1 += c1[idx];
        }
    }
}

// ---------------------------------------------------------------------------
// Phase 1. blockIdx.y = source. Each warp handles 2 consecutive reads per
// iteration. Lane (qp=lane>>2, rp=lane&3) loads float4 at float offset
// r*384 + rp*32 + 4*qp (+128, +256): 512B coalesced spans whose components
// ARE the m16n8k8 B-fragments (u[j] = T[c, l=4*qp+j]). No shared memory.
// Epilogue: relu+col-sum in C-fragments, W2 fold per lane, one 5-level
// butterfly, lane 0 stores float4 covering both reads.
// ---------------------------------------------------------------------------
__global__ __launch_bounds__(256) void rc_phase1(
    const float* __restrict__ t0, const float* __restrict__ t1,
    const float* __restrict__ W0, const float* __restrict__ b0,
    const float* __restrict__ W1, const float* __restrict__ b1,
    const float* __restrict__ W2, int R)
{
    const int s = blockIdx.y;
    const float* T  = s ? t1 : t0;
    const float* W  = s ? W1 : W0;
    const float* Bv = s ? b1 : b0;
    float2* Out     = s ? g_q1 : g_q0;

    const int tid = threadIdx.x, wid = tid >> 5, lane = tid & 31;
    const int qp = lane >> 2, rp = lane & 3;

    // A fragments af[m_tile][k_step][0..3] (bias rides channel c==12)
    uint32_t af[2][2][4];
    #pragma unroll
    for (int m = 0; m < 2; m++) {
        int r0 = qp + 16 * m, r1 = r0 + 8;
        af[m][0][0] = f2tf32(W[r0 * 12 + rp]);
        af[m][0][1] = f2tf32(W[r1 * 12 + rp]);
        af[m][0][2] = f2tf32(W[r0 * 12 + rp + 4]);
        af[m][0][3] = f2tf32(W[r1 * 12 + rp + 4]);
        af[m][1][0] = f2tf32(W[r0 * 12 + rp + 8]);
        af[m][1][1] = f2tf32(W[r1 * 12 + rp + 8]);
        af[m][1][2] = (rp == 0) ? f2tf32(Bv[r0]) : 0u;
        af[m][1][3] = (rp == 0) ? f2tf32(Bv[r1]) : 0u;
    }
    const uint32_t bk1 = (rp == 0) ? f2tf32(1.0f) : 0u;

    // W2 head weights for this lane's d-slots (d = 8i + qp)
    float w2a[4], w2b[4];
    #pragma unroll
    for (int i = 0; i < 4; i++) {
        w2a[i] = W2[s * 32 + 8 * i + qp];
        w2b[i] = W2[64 + s * 32 + 8 * i + qp];
    }

    const int lofs = rp * 32 + 4 * qp;     // lane's float offset within a read
    const int stride = gridDim.x * 16;     // 8 warps * 2 reads per block

    for (int r = (blockIdx.x * 8 + wid) * 2; r < R; r += stride) {
        const float* pA = T + (size_t)r * 384 + lofs;
        const bool hasB = (r + 1 < R);
        float4 a0 = *(const float4*)pA;
        float4 a1 = *(const float4*)(pA + 128);
        float4 a2 = *(const float4*)(pA + 256);
        float4 e0 = make_float4(0.f, 0.f, 0.f, 0.f), e1 = e0, e2 = e0;
        if (hasB) {
            e0 = *(const float4*)(pA + 384);
            e1 = *(const float4*)(pA + 512);
            e2 = *(const float4*)(pA + 640);
        }

        uint32_t uA0[4] = {f2tf32(a0.x), f2tf32(a0.y), f2tf32(a0.z), f2tf32(a0.w)};
        uint32_t uA1[4] = {f2tf32(a1.x), f2tf32(a1.y), f2tf32(a1.z), f2tf32(a1.w)};
        uint32_t uA2[4] = {f2tf32(a2.x), f2tf32(a2.y), f2tf32(a2.z), f2tf32(a2.w)};
        uint32_t uB0[4] = {f2tf32(e0.x), f2tf32(e0.y), f2tf32(e0.z), f2tf32(e0.w)};
        uint32_t uB1[4] = {f2tf32(e1.x), f2tf32(e1.y), f2tf32(e1.z), f2tf32(e1.w)};
        uint32_t uB2[4] = {f2tf32(e2.x), f2tf32(e2.y), f2tf32(e2.z), f2tf32(e2.w)};

        float accA[4] = {0.f, 0.f, 0.f, 0.f};
        float accB[4] = {0.f, 0.f, 0.f, 0.f};
        #pragma unroll
        for (int j = 0; j < 4; j++) {
            #pragma unroll
            for (int m = 0; m < 2; m++) {
                float c[4] = {0.f, 0.f, 0.f, 0.f};
                mma_tf32(c, af[m][0], uA0[j], uA1[j]);
                mma_tf32(c, af[m][1], uA2[j], bk1);
                accA[2 * m]     += fmaxf(c[0], 0.f) + fmaxf(c[1], 0.f);
                accA[2 * m + 1] += fmaxf(c[2], 0.f) + fmaxf(c[3], 0.f);
                float d[4] = {0.f, 0.f, 0.f, 0.f};
                mma_tf32(d, af[m][0], uB0[j], uB1[j]);
                mma_tf32(d, af[m][1], uB2[j], bk1);
                accB[2 * m]     += fmaxf(d[0], 0.f) + fmaxf(d[1], 0.f);
                accB[2 * m + 1] += fmaxf(d[2], 0.f) + fmaxf(d[3], 0.f);
            }
        }
        // W2 fold per lane, then one full 32-lane butterfly per value
        float qA0 = accA[0] * w2a[0] + accA[1] * w2a[1]
                  + accA[2] * w2a[2] + accA[3] * w2a[3];
        float qA1 = accA[0] * w2b[0] + accA[1] * w2b[1]
                  + accA[2] * w2b[2] + accA[3] * w2b[3];
        float qB0 = accB[0] * w2a[0] + accB[1] * w2a[1]
                  + accB[2] * w2a[2] + accB[3] * w2a[3];
        float qB1 = accB[0] * w2b[0] + accB[1] * w2b[1]
                  + accB[2] * w2b[2] + accB[3] * w2b[3];
        #pragma unroll
        for (int o = 1; o <= 16; o <<= 1) {
            qA0 += __shfl_xor_sync(0xffffffffu, qA0, o);
            qA1 += __shfl_xor_sync(0xffffffffu, qA1, o);
            qB0 += __shfl_xor_sync(0xffffffffu, qB0, o);
            qB1 += __shfl_xor_sync(0xffffffffu, qB1, o);
        }
        if (lane == 0) {
            if (hasB) {
                *(float4*)&Out[r] = make_float4(qA0, qA1, qB0, qB1);
            } else {
                Out[r] = make_float2(qA0, qA1);
            }
        }
    }
}

// ---------------------------------------------------------------------------
// Phase 2: one warp per allele (8 per block, grid = A/8). Offsets are
// precomputed; lanes gather the per-read float2 partials in parallel.
// ---------------------------------------------------------------------------
__global__ __launch_bounds__(256) void rc_phase2(
    const int* __restrict__ cnt0, const int* __restrict__ cnt1,
    const float* __restrict__ dm0, const float* __restrict__ dm1,
    const float* __restrict__ b2, float* __restrict__ out, int A)
{
    const int tid = threadIdx.x, wid = tid >> 5, lane = tid & 31;
    const int a = blockIdx.x * 8 + wid;
    if (a >= A) return;

    const int off0 = g_offs0[a], off1 = g_offs1[a];
    const int c0 = cnt0[a], c1 = cnt1[a];

    float s00 = 0.f, s01 = 0.f, s10 = 0.f, s11 = 0.f;
    for (int i = lane; i < c0; i += 32) {
        float2 v = g_q0[off0 + i]; s00 += v.x; s01 += v.y;
    }
    for (int i = lane; i < c1; i += 32) {
        float2 v = g_q1[off1 + i]; s10 += v.x; s11 += v.y;
    }
    #pragma unroll
    for (int o = 16; o; o >>= 1) {
        s00 += __shfl_xor_sync(0xffffffffu, s00, o);
        s01 += __shfl_xor_sync(0xffffffffu, s01, o);
        s10 += __shfl_xor_sync(0xffffffffu, s10, o);
        s11 += __shfl_xor_sync(0xffffffffu, s11, o);
    }
    if (lane == 0) {
        const float n0 = 1.0f / (dm0[a] * 32.f);
        const float n1 = 1.0f / (dm1[a] * 32.f);
        out[2 * a]     = b2[0] + s00 * n0 + s10 * n1;
        out[2 * a + 1] = b2[1] + s01 * n0 + s11 * n1;
    }
}

// ---------------------------------------------------------------------------
extern "C" void kernel_launch(void* const* d_in, const int* in_sizes, int n_in,
                              void* d_out, int out_size) {
    const float* t0  = (const float*)d_in[0];
    const float* t1  = (const float*)d_in[1];
    const float* W0  = (const float*)d_in[2];
    const float* b0  = (const float*)d_in[3];
    const float* W1  = (const float*)d_in[4];
    const float* b1  = (const float*)d_in[5];
    const float* W2  = (const float*)d_in[6];
    const float* b2  = (const float*)d_in[7];
    const int*   c0  = (const int*)d_in[8];
    const int*   c1  = (const int*)d_in[9];
    const float* dm0 = (const float*)d_in[11];
    const float* dm1 = (const float*)d_in[12];
    float* out = (float*)d_out;

    const int A = in_sizes[8];
    const int R = in_sizes[0] / 384;   // reads per source (C*L = 384)

    rc_scan<<<1, 256>>>(c0, c1, A);
    dim3 grid1(1024, 2);
    rc_phase1<<<grid1, 256>>>(t0, t1, W0, b0, W1, b1, W2, R);
    rc_phase2<<<(A + 7) / 8, 256>>>(c0, c1, dm0, dm1, b2, out, A);
}

// round 8
// speedup vs baseline: 1.1999x; 1.1999x over previous
#include <cuda_runtime.h>
#include <cstdint>

// ---------------------------------------------------------------------------
// C=12, L=32, D=32, NOUT=2. Counts are int32 on device (JAX x64-off).
// scan1  : per-256-chunk inclusive scans -> local offsets + chunk totals
// phase1 : dense per-read q[r][2] = W2_s . relu(W x_r + b) summed over L
//          (cp.async 3-stage per-warp pipeline; measured-best variant)
// phase2 : warp-per-allele ragged reduce; base offset from chunk totals
// ---------------------------------------------------------------------------

#define MAXR 131072
#define MAXA 16384
__device__ float2 g_q0[MAXR];
__device__ float2 g_q1[MAXR];
__device__ int g_loc0[MAXA];    // exclusive offset within 256-chunk
__device__ int g_loc1[MAXA];
__device__ int g_btot0[MAXA / 256 + 1];   // per-chunk totals
__device__ int g_btot1[MAXA / 256 + 1];

__device__ __forceinline__ uint32_t f2tf32(float f) {
    uint32_t u;
    asm("cvt.rna.tf32.f32 %0, %1;" : "=r"(u) : "f"(f));
    return u;
}

__device__ __forceinline__ void mma_tf32(float c[4], const uint32_t a[4],
                                         uint32_t b0, uint32_t b1) {
    asm volatile(
        "mma.sync.aligned.m16n8k8.row.col.f32.tf32.tf32.f32 "
        "{%0,%1,%2,%3},{%4,%5,%6,%7},{%8,%9},{%0,%1,%2,%3};"
        : "+f"(c[0]), "+f"(c[1]), "+f"(c[2]), "+f"(c[3])
        : "r"(a[0]), "r"(a[1]), "r"(a[2]), "r"(a[3]), "r"(b0), "r"(b1));
}

__device__ __forceinline__ void cp16(uint32_t smem_addr, const void* g) {
    asm volatile("cp.async.ca.shared.global [%0], [%1], 16;"
                 :: "r"(smem_addr), "l"(g));
}

// ---------------------------------------------------------------------------
// Level-1 scan: one block per 256-allele chunk.
// ---------------------------------------------------------------------------
__global__ __launch_bounds__(256) void rc_scan1(const int* __restrict__ c0,
                                                const int* __restrict__ c1,
                                                int A) {
    __shared__ int s0[256], s1[256];
    const int t = threadIdx.x;
    const int a = blockIdx.x * 256 + t;
    const int v0 = (a < A) ? c0[a] : 0;
    const int v1 = (a < A) ? c1[a] : 0;
    s0[t] = v0; s1[t] = v1;
    __syncthreads();
    #pragma unroll
    for (int o = 1; o < 256; o <<= 1) {
        int p0 = (t >= o) ? s0[t - o] : 0;
        int p1 = (t >= o) ? s1[t - o] : 0;
        __syncthreads();
        s0[t] += p0; s1[t] += p1;
        __syncthreads();
    }
    if (a < A) { g_loc0[a] = s0[t] - v0; g_loc1[a] = s1[t] - v1; }
    if (t == 255) { g_btot0[blockIdx.x] = s0[255]; g_btot1[blockIdx.x] = s1[255]; }
}

// ---------------------------------------------------------------------------
// Phase 1 (measured-best round-6 variant). blockIdx.y = source.
// Per warp per read (1536B): 3x cp.async (512B, XOR-swizzled dst) ->
// wait/syncwarp -> 3x LDS.128 -> 12 cvt -> 16 tf32 MMAs -> relu+col-sum ->
// warp folds -> W2 head fold -> one STG.64.
// ---------------------------------------------------------------------------
__global__ __launch_bounds__(256) void rc_phase1(
    const float* __restrict__ t0, const float* __restrict__ t1,
    const float* __restrict__ W0, const float* __restrict__ b0,
    const float* __restrict__ W1, const float* __restrict__ b1,
    const float* __restrict__ W2, int R)
{
    const int s = blockIdx.y;
    const float* T  = s ? t1 : t0;
    const float* W  = s ? W1 : W0;
    const float* Bv = s ? b1 : b0;
    float2* Out     = s ? g_q1 : g_q0;

    const int tid  = threadIdx.x;
    const int wid  = tid >> 5, lane = tid & 31;
    const int qp   = lane >> 2, rp = lane & 3;
    const int g    = lane >> 3, h = lane & 7;

    __shared__ float4 buf[8][3][96];

    uint32_t af[2][2][4];
    #pragma unroll
    for (int m = 0; m < 2; m++) {
        int r0 = qp + 16 * m, r1 = r0 + 8;
        af[m][0][0] = f2tf32(W[r0 * 12 + rp]);
        af[m][0][1] = f2tf32(W[r1 * 12 + rp]);
        af[m][0][2] = f2tf32(W[r0 * 12 + rp + 4]);
        af[m][0][3] = f2tf32(W[r1 * 12 + rp + 4]);
        af[m][1][0] = f2tf32(W[r0 * 12 + rp + 8]);
        af[m][1][1] = f2tf32(W[r1 * 12 + rp + 8]);
        af[m][1][2] = (rp == 0) ? f2tf32(Bv[r0]) : 0u;
        af[m][1][3] = (rp == 0) ? f2tf32(Bv[r1]) : 0u;
    }
    const uint32_t bk1 = (rp == 0) ? f2tf32(1.0f) : 0u;

    float w2a[4], w2b[4];
    #pragma unroll
    for (int i = 0; i < 4; i++) {
        w2a[i] = W2[s * 32 + 8 * i + qp];
        w2b[i] = W2[64 + s * 32 + 8 * i + qp];
    }

    const int sw_st = h ^ (2 * g);
    const int sts0 = g * 8 + sw_st, sts1 = (g + 4) * 8 + sw_st,
              sts2 = (g + 8) * 8 + sw_st;
    const int sw_ld = qp ^ (2 * rp);
    const int lds0 = rp * 8 + sw_ld, lds1 = (rp + 4) * 8 + sw_ld,
              lds2 = (rp + 8) * 8 + sw_ld;

    uint32_t dst[3][3];
    #pragma unroll
    for (int st = 0; st < 3; st++) {
        dst[st][0] = (uint32_t)__cvta_generic_to_shared(&buf[wid][st][sts0]);
        dst[st][1] = (uint32_t)__cvta_generic_to_shared(&buf[wid][st][sts1]);
        dst[st][2] = (uint32_t)__cvta_generic_to_shared(&buf[wid][st][sts2]);
    }

    const int WT = gridDim.x * 8;
    const int r0w = blockIdx.x * 8 + wid;

    #pragma unroll
    for (int st = 0; st < 2; st++) {
        int rr = r0w + st * WT;
        if (rr < R) {
            const float4* p = (const float4*)T + (size_t)rr * 96;
            cp16(dst[st][0], p + g * 8 + h);
            cp16(dst[st][1], p + (g + 4) * 8 + h);
            cp16(dst[st][2], p + (g + 8) * 8 + h);
        }
        asm volatile("cp.async.commit_group;" ::: "memory");
    }

    int r = r0w, stage = 0;
    while (r < R) {
        {
            int rr = r + 2 * WT;
            int st = stage + 2; if (st >= 3) st -= 3;
            if (rr < R) {
                const float4* p = (const float4*)T + (size_t)rr * 96;
                cp16(dst[st][0], p + g * 8 + h);
                cp16(dst[st][1], p + (g + 4) * 8 + h);
                cp16(dst[st][2], p + (g + 8) * 8 + h);
            }
            asm volatile("cp.async.commit_group;" ::: "memory");
        }
        asm volatile("cp.async.wait_group 2;" ::: "memory");
        __syncwarp();

        const float4* B = buf[wid][stage];
        float4 x0 = B[lds0], x1 = B[lds1], x2 = B[lds2];
        uint32_t u0[4] = {f2tf32(x0.x), f2tf32(x0.y), f2tf32(x0.z), f2tf32(x0.w)};
        uint32_t u1[4] = {f2tf32(x1.x), f2tf32(x1.y), f2tf32(x1.z), f2tf32(x1.w)};
        uint32_t u2[4] = {f2tf32(x2.x), f2tf32(x2.y), f2tf32(x2.z), f2tf32(x2.w)};

        float acc[4] = {0.f, 0.f, 0.f, 0.f};
        #pragma unroll
        for (int j = 0; j < 4; j++) {
            #pragma unroll
            for (int m = 0; m < 2; m++) {
                float c[4] = {0.f, 0.f, 0.f, 0.f};
                mma_tf32(c, af[m][0], u0[j], u1[j]);
                mma_tf32(c, af[m][1], u2[j], bk1);
                acc[2 * m]     += fmaxf(c[0], 0.f) + fmaxf(c[1], 0.f);
                acc[2 * m + 1] += fmaxf(c[2], 0.f) + fmaxf(c[3], 0.f);
            }
        }
        #pragma unroll
        for (int i = 0; i < 4; i++) {
            acc[i] += __shfl_xor_sync(0xffffffffu, acc[i], 1);
            acc[i] += __shfl_xor_sync(0xffffffffu, acc[i], 2);
        }
        float q0 = acc[0] * w2a[0] + acc[1] * w2a[1]
                 + acc[2] * w2a[2] + acc[3] * w2a[3];
        float q1 = acc[0] * w2b[0] + acc[1] * w2b[1]
                 + acc[2] * w2b[2] + acc[3] * w2b[3];
        #pragma unroll
        for (int o = 4; o <= 16; o <<= 1) {
            q0 += __shfl_xor_sync(0xffffffffu, q0, o);
            q1 += __shfl_xor_sync(0xffffffffu, q1, o);
        }
        if (lane == 0) Out[r] = make_float2(q0, q1);

        r += WT;
        stage++; if (stage >= 3) stage = 0;
    }
}

// ---------------------------------------------------------------------------
// Phase 2: warp-per-allele (8/block). All 8 alleles share one 256-chunk,
// so base = sum of preceding chunk totals (lane-strided + butterfly),
// offset = base + local exclusive offset.
// ---------------------------------------------------------------------------
__global__ __launch_bounds__(256) void rc_phase2(
    const int* __restrict__ cnt0, const int* __restrict__ cnt1,
    const float* __restrict__ dm0, const float* __restrict__ dm1,
    const float* __restrict__ b2, float* __restrict__ out, int A)
{
    const int tid = threadIdx.x, wid = tid >> 5, lane = tid & 31;
    const int a = blockIdx.x * 8 + wid;
    if (a >= A) return;

    const int chunk = (blockIdx.x * 8) >> 8;   // same for all warps in block
    int v0 = 0, v1 = 0;
    for (int j = lane; j < chunk; j += 32) { v0 += g_btot0[j]; v1 += g_btot1[j]; }
    #pragma unroll
    for (int o = 16; o; o >>= 1) {
        v0 += __shfl_xor_sync(0xffffffffu, v0, o);
        v1 += __shfl_xor_sync(0xffffffffu, v1, o);
    }

    const int off0 = v0 + g_loc0[a];
    const int off1 = v1 + g_loc1[a];
    const int c0 = cnt0[a], c1 = cnt1[a];

    float s00 = 0.f, s01 = 0.f, s10 = 0.f, s11 = 0.f;
    for (int i = lane; i < c0; i += 32) {
        float2 v = g_q0[off0 + i]; s00 += v.x; s01 += v.y;
    }
    for (int i = lane; i < c1; i += 32) {
        float2 v = g_q1[off1 + i]; s10 += v.x; s11 += v.y;
    }
    #pragma unroll
    for (int o = 16; o; o >>= 1) {
        s00 += __shfl_xor_sync(0xffffffffu, s00, o);
        s01 += __shfl_xor_sync(0xffffffffu, s01, o);
        s10 += __shfl_xor_sync(0xffffffffu, s10, o);
        s11 += __shfl_xor_sync(0xffffffffu, s11, o);
    }
    if (lane == 0) {
        const float n0 = 1.0f / (dm0[a] * 32.f);
        const float n1 = 1.0f / (dm1[a] * 32.f);
        out[2 * a]     = b2[0] + s00 * n0 + s10 * n1;
        out[2 * a + 1] = b2[1] + s01 * n0 + s11 * n1;
    }
}

// ---------------------------------------------------------------------------
extern "C" void kernel_launch(void* const* d_in, const int* in_sizes, int n_in,
                              void* d_out, int out_size) {
    const float* t0  = (const float*)d_in[0];
    const float* t1  = (const float*)d_in[1];
    const float* W0  = (const float*)d_in[2];
    const float* b0  = (const float*)d_in[3];
    const float* W1  = (const float*)d_in[4];
    const float* b1  = (const float*)d_in[5];
    const float* W2  = (const float*)d_in[6];
    const float* b2  = (const float*)d_in[7];
    const int*   c0  = (const int*)d_in[8];
    const int*   c1  = (const int*)d_in[9];
    const float* dm0 = (const float*)d_in[11];
    const float* dm1 = (const float*)d_in[12];
    float* out = (float*)d_out;

    const int A = in_sizes[8];
    const int R = in_sizes[0] / 384;   // reads per source (C*L = 384)

    rc_scan1<<<(A + 255) / 256, 256>>>(c0, c1, A);
    dim3 grid1(1024, 2);
    rc_phase1<<<grid1, 256>>>(t0, t1, W0, b0, W1, b1, W2, R);
    rc_phase2<<<(A + 7) / 8, 256>>>(c0, c1, dm0, dm1, b2, out, A);
}

// round 9
// speedup vs baseline: 1.2764x; 1.0637x over previous
#include <cuda_runtime.h>
#include <cstdint>

// ---------------------------------------------------------------------------
// C=12, L=32, D=32, NOUT=2. Counts are int32 on device (JAX x64-off).
// phase1 : dense per-read q[r][2] = W2_s . relu(W x_r + b) summed over L
//          (cp.async 3-stage per-warp pipeline). 16 extra blocks in the same
//          grid perform the count scans (hidden under the stream).
// phase2 : warp-per-allele ragged reduce; base offset from chunk totals.
// ---------------------------------------------------------------------------

#define MAXR 131072
#define MAXA 16384
#define GX   1024              // streaming blocks in grid.x
__device__ float2 g_q0[MAXR];
__device__ float2 g_q1[MAXR];
__device__ int g_loc0[MAXA];             // exclusive offset within 256-chunk
__device__ int g_loc1[MAXA];
__device__ int g_btot0[MAXA / 256 + 1];  // per-chunk totals
__device__ int g_btot1[MAXA / 256 + 1];

__device__ __forceinline__ uint32_t f2tf32(float f) {
    uint32_t u;
    asm("cvt.rna.tf32.f32 %0, %1;" : "=r"(u) : "f"(f));
    return u;
}

__device__ __forceinline__ void mma_tf32(float c[4], const uint32_t a[4],
                                         uint32_t b0, uint32_t b1) {
    asm volatile(
        "mma.sync.aligned.m16n8k8.row.col.f32.tf32.tf32.f32 "
        "{%0,%1,%2,%3},{%4,%5,%6,%7},{%8,%9},{%0,%1,%2,%3};"
        : "+f"(c[0]), "+f"(c[1]), "+f"(c[2]), "+f"(c[3])
        : "r"(a[0]), "r"(a[1]), "r"(a[2]), "r"(a[3]), "r"(b0), "r"(b1));
}

__device__ __forceinline__ void cp16(uint32_t smem_addr, const void* g) {
    asm volatile("cp.async.ca.shared.global [%0], [%1], 16;"
                 :: "r"(smem_addr), "l"(g));
}

// ---------------------------------------------------------------------------
// Phase 1. blockIdx.y = source; blockIdx.x < GX streams reads, otherwise
// (y==0) the block scans one 256-allele count chunk and exits.
// Streaming, per warp per read (1536B): 3x cp.async (512B, XOR-swizzled) ->
// wait/syncwarp -> 3x LDS.128 -> 12 cvt -> 16 tf32 MMAs -> relu+col-sum ->
// per-lane W2 dot -> one 5-level butterfly -> lane0 STG.64.
// ---------------------------------------------------------------------------
__global__ __launch_bounds__(256) void rc_phase1(
    const float* __restrict__ t0, const float* __restrict__ t1,
    const float* __restrict__ W0, const float* __restrict__ b0,
    const float* __restrict__ W1, const float* __restrict__ b1,
    const float* __restrict__ W2,
    const int* __restrict__ cnt0, const int* __restrict__ cnt1,
    int R, int A)
{
    const int tid  = threadIdx.x;

    // ---- scan side-blocks (hidden under the streaming wave) ----
    if (blockIdx.x >= GX) {
        if (blockIdx.y != 0) return;
        const int chunk = blockIdx.x - GX;
        __shared__ int s0[256], s1[256];
        const int a = chunk * 256 + tid;
        const int v0 = (a < A) ? cnt0[a] : 0;
        const int v1 = (a < A) ? cnt1[a] : 0;
        s0[tid] = v0; s1[tid] = v1;
        __syncthreads();
        #pragma unroll
        for (int o = 1; o < 256; o <<= 1) {
            int p0 = (tid >= o) ? s0[tid - o] : 0;
            int p1 = (tid >= o) ? s1[tid - o] : 0;
            __syncthreads();
            s0[tid] += p0; s1[tid] += p1;
            __syncthreads();
        }
        if (a < A) { g_loc0[a] = s0[tid] - v0; g_loc1[a] = s1[tid] - v1; }
        if (tid == 255) { g_btot0[chunk] = s0[255]; g_btot1[chunk] = s1[255]; }
        return;
    }

    // ---- streaming ----
    const int s = blockIdx.y;
    const float* T  = s ? t1 : t0;
    const float* W  = s ? W1 : W0;
    const float* Bv = s ? b1 : b0;
    float2* Out     = s ? g_q1 : g_q0;

    const int wid  = tid >> 5, lane = tid & 31;
    const int qp   = lane >> 2, rp = lane & 3;
    const int g    = lane >> 3, h = lane & 7;

    __shared__ float4 buf[8][3][96];

    uint32_t af[2][2][4];
    #pragma unroll
    for (int m = 0; m < 2; m++) {
        int r0 = qp + 16 * m, r1 = r0 + 8;
        af[m][0][0] = f2tf32(W[r0 * 12 + rp]);
        af[m][0][1] = f2tf32(W[r1 * 12 + rp]);
        af[m][0][2] = f2tf32(W[r0 * 12 + rp + 4]);
        af[m][0][3] = f2tf32(W[r1 * 12 + rp + 4]);
        af[m][1][0] = f2tf32(W[r0 * 12 + rp + 8]);
        af[m][1][1] = f2tf32(W[r1 * 12 + rp + 8]);
        af[m][1][2] = (rp == 0) ? f2tf32(Bv[r0]) : 0u;
        af[m][1][3] = (rp == 0) ? f2tf32(Bv[r1]) : 0u;
    }
    const uint32_t bk1 = (rp == 0) ? f2tf32(1.0f) : 0u;

    float w2a[4], w2b[4];
    #pragma unroll
    for (int i = 0; i < 4; i++) {
        w2a[i] = W2[s * 32 + 8 * i + qp];
        w2b[i] = W2[64 + s * 32 + 8 * i + qp];
    }

    const int sw_st = h ^ (2 * g);
    const int sts0 = g * 8 + sw_st, sts1 = (g + 4) * 8 + sw_st,
              sts2 = (g + 8) * 8 + sw_st;
    const int sw_ld = qp ^ (2 * rp);
    const int lds0 = rp * 8 + sw_ld, lds1 = (rp + 4) * 8 + sw_ld,
              lds2 = (rp + 8) * 8 + sw_ld;

    uint32_t dst[3][3];
    #pragma unroll
    for (int st = 0; st < 3; st++) {
        dst[st][0] = (uint32_t)__cvta_generic_to_shared(&buf[wid][st][sts0]);
        dst[st][1] = (uint32_t)__cvta_generic_to_shared(&buf[wid][st][sts1]);
        dst[st][2] = (uint32_t)__cvta_generic_to_shared(&buf[wid][st][sts2]);
    }

    const int WT = GX * 8;
    const int r0w = blockIdx.x * 8 + wid;

    #pragma unroll
    for (int st = 0; st < 2; st++) {
        int rr = r0w + st * WT;
        if (rr < R) {
            const float4* p = (const float4*)T + (size_t)rr * 96;
            cp16(dst[st][0], p + g * 8 + h);
            cp16(dst[st][1], p + (g + 4) * 8 + h);
            cp16(dst[st][2], p + (g + 8) * 8 + h);
        }
        asm volatile("cp.async.commit_group;" ::: "memory");
    }

    int r = r0w, stage = 0;
    while (r < R) {
        {
            int rr = r + 2 * WT;
            int st = stage + 2; if (st >= 3) st -= 3;
            if (rr < R) {
                const float4* p = (const float4*)T + (size_t)rr * 96;
                cp16(dst[st][0], p + g * 8 + h);
                cp16(dst[st][1], p + (g + 4) * 8 + h);
                cp16(dst[st][2], p + (g + 8) * 8 + h);
            }
            asm volatile("cp.async.commit_group;" ::: "memory");
        }
        asm volatile("cp.async.wait_group 2;" ::: "memory");
        __syncwarp();

        const float4* B = buf[wid][stage];
        float4 x0 = B[lds0], x1 = B[lds1], x2 = B[lds2];
        uint32_t u0[4] = {f2tf32(x0.x), f2tf32(x0.y), f2tf32(x0.z), f2tf32(x0.w)};
        uint32_t u1[4] = {f2tf32(x1.x), f2tf32(x1.y), f2tf32(x1.z), f2tf32(x1.w)};
        uint32_t u2[4] = {f2tf32(x2.x), f2tf32(x2.y), f2tf32(x2.z), f2tf32(x2.w)};

        float acc[4] = {0.f, 0.f, 0.f, 0.f};
        #pragma unroll
        for (int j = 0; j < 4; j++) {
            #pragma unroll
            for (int m = 0; m < 2; m++) {
                float c[4] = {0.f, 0.f, 0.f, 0.f};
                mma_tf32(c, af[m][0], u0[j], u1[j]);
                mma_tf32(c, af[m][1], u2[j], bk1);
                acc[2 * m]     += fmaxf(c[0], 0.f) + fmaxf(c[1], 0.f);
                acc[2 * m + 1] += fmaxf(c[2], 0.f) + fmaxf(c[3], 0.f);
            }
        }
        // per-lane W2 dot (acc[i] = partial sum for d=8i+qp over this lane's
        // l-subset), then one full butterfly sums over all d and l.
        float q0 = acc[0] * w2a[0] + acc[1] * w2a[1]
                 + acc[2] * w2a[2] + acc[3] * w2a[3];
        float q1 = acc[0] * w2b[0] + acc[1] * w2b[1]
                 + acc[2] * w2b[2] + acc[3] * w2b[3];
        #pragma unroll
        for (int o = 1; o <= 16; o <<= 1) {
            q0 += __shfl_xor_sync(0xffffffffu, q0, o);
            q1 += __shfl_xor_sync(0xffffffffu, q1, o);
        }
        if (lane == 0) Out[r] = make_float2(q0, q1);

        r += WT;
        stage++; if (stage >= 3) stage = 0;
    }
}

// ---------------------------------------------------------------------------
// Phase 2: warp-per-allele (8/block). All 8 alleles share one 256-chunk,
// so base = sum of preceding chunk totals, offset = base + local offset.
// ---------------------------------------------------------------------------
__global__ __launch_bounds__(256) void rc_phase2(
    const int* __restrict__ cnt0, const int* __restrict__ cnt1,
    const float* __restrict__ dm0, const float* __restrict__ dm1,
    const float* __restrict__ b2, float* __restrict__ out, int A)
{
    const int tid = threadIdx.x, wid = tid >> 5, lane = tid & 31;
    const int a = blockIdx.x * 8 + wid;
    if (a >= A) return;

    const int chunk = (blockIdx.x * 8) >> 8;
    int v0 = 0, v1 = 0;
    for (int j = lane; j < chunk; j += 32) { v0 += g_btot0[j]; v1 += g_btot1[j]; }
    #pragma unroll
    for (int o = 16; o; o >>= 1) {
        v0 += __shfl_xor_sync(0xffffffffu, v0, o);
        v1 += __shfl_xor_sync(0xffffffffu, v1, o);
    }

    const int off0 = v0 + g_loc0[a];
    const int off1 = v1 + g_loc1[a];
    const int c0 = cnt0[a], c1 = cnt1[a];

    float s00 = 0.f, s01 = 0.f, s10 = 0.f, s11 = 0.f;
    for (int i = lane; i < c0; i += 32) {
        float2 v = g_q0[off0 + i]; s00 += v.x; s01 += v.y;
    }
    for (int i = lane; i < c1; i += 32) {
        float2 v = g_q1[off1 + i]; s10 += v.x; s11 += v.y;
    }
    #pragma unroll
    for (int o = 16; o; o >>= 1) {
        s00 += __shfl_xor_sync(0xffffffffu, s00, o);
        s01 += __shfl_xor_sync(0xffffffffu, s01, o);
        s10 += __shfl_xor_sync(0xffffffffu, s10, o);
        s11 += __shfl_xor_sync(0xffffffffu, s11, o);
    }
    if (lane == 0) {
        const float n0 = 1.0f / (dm0[a] * 32.f);
        const float n1 = 1.0f / (dm1[a] * 32.f);
        out[2 * a]     = b2[0] + s00 * n0 + s10 * n1;
        out[2 * a + 1] = b2[1] + s01 * n0 + s11 * n1;
    }
}

// ---------------------------------------------------------------------------
extern "C" void kernel_launch(void* const* d_in, const int* in_sizes, int n_in,
                              void* d_out, int out_size) {
    const float* t0  = (const float*)d_in[0];
    const float* t1  = (const float*)d_in[1];
    const float* W0  = (const float*)d_in[2];
    const float* b0  = (const float*)d_in[3];
    const float* W1  = (const float*)d_in[4];
    const float* b1  = (const float*)d_in[5];
    const float* W2  = (const float*)d_in[6];
    const float* b2  = (const float*)d_in[7];
    const int*   c0  = (const int*)d_in[8];
    const int*   c1  = (const int*)d_in[9];
    const float* dm0 = (const float*)d_in[11];
    const float* dm1 = (const float*)d_in[12];
    float* out = (float*)d_out;

    const int A = in_sizes[8];
    const int R = in_sizes[0] / 384;   // reads per source (C*L = 384)
    const int nChunks = (A + 255) / 256;

    dim3 grid1(GX + nChunks, 2);
    rc_phase1<<<grid1, 256>>>(t0, t1, W0, b0, W1, b1, W2, c0, c1, R, A);
    rc_phase2<<<(A + 7) / 8, 256>>>(c0, c1, dm0, dm1, b2, out, A);
}